// round 5
// baseline (speedup 1.0000x reference)
#include <cuda_runtime.h>
#include <cuda_bf16.h>
#include <cstdint>

#define B_ 8
#define E_ 2048
#define N_ 2048
#define F_ 128

// Y = X @ W^T stored transposed [b][f][n], split hi/lo bf16 (device scratch).
__device__ __align__(16) __nv_bfloat16 g_Yh[B_ * F_ * N_];
__device__ __align__(16) __nv_bfloat16 g_Yl[B_ * F_ * N_];

extern __shared__ __align__(16) char g_smem[];

// ---------------- helpers (plain sm_103 features only) ----------------
__device__ __forceinline__ uint32_t smem_u32(const void* p) {
    uint32_t a;
    asm("{ .reg .u64 t; cvta.to.shared.u64 t, %1; cvt.u32.u64 %0, t; }" : "=r"(a) : "l"(p));
    return a;
}
#define SWZ(x) ((x) ^ (((x) >> 3) & 0x70))

#define CP16(dst, src) \
    asm volatile("cp.async.ca.shared.global [%0], [%1], 16;" :: "r"(dst), "l"(src))
#define CP_COMMIT() asm volatile("cp.async.commit_group;" ::: "memory")
#define CP_WAIT1()  asm volatile("cp.async.wait_group 1;" ::: "memory")
#define CP_WAIT0()  asm volatile("cp.async.wait_group 0;" ::: "memory")

#define LDSM_X4(r0, r1, r2, r3, addr) \
    asm volatile("ldmatrix.sync.aligned.m8n8.x4.shared.b16 {%0,%1,%2,%3}, [%4];" \
                 : "=r"(r0), "=r"(r1), "=r"(r2), "=r"(r3) : "r"(addr))

#define MMA_BF16(d, a, b0, b1) \
    asm volatile("mma.sync.aligned.m16n8k16.row.col.f32.bf16.bf16.f32 " \
                 "{%0,%1,%2,%3}, {%4,%5,%6,%7}, {%8,%9}, {%0,%1,%2,%3};" \
                 : "+f"((d)[0]), "+f"((d)[1]), "+f"((d)[2]), "+f"((d)[3]) \
                 : "r"((a)[0]), "r"((a)[1]), "r"((a)[2]), "r"((a)[3]), \
                   "r"(b0), "r"(b1))

__device__ __forceinline__ void sts128(uint32_t a, uint4 v) {
    asm volatile("st.shared.v4.b32 [%0], {%1, %2, %3, %4};"
                 :: "r"(a), "r"(v.x), "r"(v.y), "r"(v.z), "r"(v.w));
}

// ---------------- Prologue: Y = X @ W^T, hi/lo bf16, transposed store ----------------
#define STRX 68
#define STRW 132
__global__ void __launch_bounds__(256) v2h_prologue(const float* __restrict__ X,
                                                    const float* __restrict__ W) {
    float* sXT = (float*)g_smem;          // [128 k][STRX]
    float* sWT = sXT + 128 * STRX;        // [128 k][STRW]
    int t = threadIdx.x;
    int b = blockIdx.x >> 5, n0 = (blockIdx.x & 31) << 6;
    {
        int n = t >> 2, kc = (t & 3) * 32;
        const float* xp = X + ((size_t)(b * N_ + n0 + n)) * F_ + kc;
#pragma unroll
        for (int q = 0; q < 8; q++) {
            float4 v = *(const float4*)(xp + q * 4);
            int k = kc + q * 4;
            sXT[(k + 0) * STRX + n] = v.x; sXT[(k + 1) * STRX + n] = v.y;
            sXT[(k + 2) * STRX + n] = v.z; sXT[(k + 3) * STRX + n] = v.w;
        }
        int f = t >> 1, kc2 = (t & 1) * 64;
        const float* wp = W + f * F_ + kc2;
#pragma unroll
        for (int q = 0; q < 16; q++) {
            float4 v = *(const float4*)(wp + q * 4);
            int k = kc2 + q * 4;
            sWT[(k + 0) * STRW + f] = v.x; sWT[(k + 1) * STRW + f] = v.y;
            sWT[(k + 2) * STRW + f] = v.z; sWT[(k + 3) * STRW + f] = v.w;
        }
    }
    __syncthreads();
    int tn = t & 15, tf = t >> 4;
    float acc[4][8];
#pragma unroll
    for (int i = 0; i < 4; i++)
#pragma unroll
        for (int j = 0; j < 8; j++) acc[i][j] = 0.f;
    for (int k = 0; k < 128; k++) {
        float4 xv = *(const float4*)&sXT[k * STRX + tn * 4];
        float4 w0 = *(const float4*)&sWT[k * STRW + tf * 8];
        float4 w1 = *(const float4*)&sWT[k * STRW + tf * 8 + 4];
        float xr[4] = {xv.x, xv.y, xv.z, xv.w};
        float wr[8] = {w0.x, w0.y, w0.z, w0.w, w1.x, w1.y, w1.z, w1.w};
#pragma unroll
        for (int i = 0; i < 4; i++)
#pragma unroll
            for (int j = 0; j < 8; j++) acc[i][j] = fmaf(xr[i], wr[j], acc[i][j]);
    }
#pragma unroll
    for (int j = 0; j < 8; j++) {
        unsigned short hb[4], lb[4];
#pragma unroll
        for (int i = 0; i < 4; i++) {
            float y = acc[i][j];
            __nv_bfloat16 hh = __float2bfloat16(y);
            hb[i] = __bfloat16_as_ushort(hh);
            lb[i] = __bfloat16_as_ushort(__float2bfloat16(y - __bfloat162float(hh)));
        }
        size_t base = ((size_t)(b * F_ + tf * 8 + j)) * N_ + n0 + tn * 4;
        uint2 uh = make_uint2((uint32_t)hb[0] | ((uint32_t)hb[1] << 16),
                              (uint32_t)hb[2] | ((uint32_t)hb[3] << 16));
        uint2 ul = make_uint2((uint32_t)lb[0] | ((uint32_t)lb[1] << 16),
                              (uint32_t)lb[2] | ((uint32_t)lb[3] << 16));
        *(uint2*)(g_Yh + base) = uh;
        *(uint2*)(g_Yl + base) = ul;
    }
}

// ---------------- Main: out = relu((mask @ Y)/norm + b) via mma.sync bf16 ----------------
// grid 128 = b*16 + etile; 256 thr = 8 warps (2M x 4N), warp tile 64x32.
// 32 stages of K=64; A(mask) LDG->STS, Yh/Yl cp.async; double-buffered smem.
__global__ void __launch_bounds__(256, 1) v2h_main(const float* __restrict__ adj,
                                                   const float* __restrict__ bias,
                                                   float* __restrict__ out) {
    uint32_t sb = smem_u32(g_smem);
    float* sNorm = (float*)g_smem;                       // 128 floats
    const uint32_t tb = (sb + 512u + 1023u) & ~1023u;    // 1024B-aligned tiles
    int t = threadIdx.x, lid = t & 31, wid = t >> 5;
    int warpM = wid >> 2, warpN = wid & 3;               // 2 x 4
    int b = blockIdx.x >> 4, e0 = (blockIdx.x & 15) << 7;

    int r = t >> 1, h = t & 1;                            // conversion mapping
    const float* ap = adj + ((size_t)(b * E_ + e0 + r)) * N_ + h * 32;
    const char* YhG = (const char*)(g_Yh + (size_t)b * F_ * N_);
    const char* YlG = (const char*)(g_Yl + (size_t)b * F_ * N_);

    // prefetch stage 0: adj regs + Y cp.async
    float4 ra[8];
#pragma unroll
    for (int q = 0; q < 8; q++) ra[q] = *(const float4*)(ap + q * 4);
    {
        uint32_t hB0 = tb + 32768u, lB0 = tb + 65536u;
#pragma unroll
        for (int i = 0; i < 4; i++) {
            int c = t + i * 256, row = c >> 3, j = c & 7;
            uint32_t d = SWZ((uint32_t)(row * 128 + j * 16));
            CP16(hB0 + d, YhG + ((size_t)row * N_ + j * 8) * 2);
            CP16(lB0 + d, YlG + ((size_t)row * N_ + j * 8) * 2);
        }
        CP_COMMIT();
    }

    float acc[4][4][4];
#pragma unroll
    for (int m = 0; m < 4; m++)
#pragma unroll
        for (int n = 0; n < 4; n++)
#pragma unroll
            for (int v = 0; v < 4; v++) acc[m][n][v] = 0.f;
    int cnt = 0;
    const uint32_t r16 = (uint32_t)(lid & 15), kb0 = (uint32_t)(lid >> 4);

    for (int s = 0; s < 32; s++) {
        int buf = s & 1;
        uint32_t aB = tb + buf * 16384u;
        uint32_t hB = tb + 32768u + buf * 16384u;
        uint32_t lB = tb + 65536u + buf * 16384u;
        __syncthreads();  // bufA[s%2] and Y buf (s+1)%2 free (readers of s-1 done)
#pragma unroll
        for (int q = 0; q < 4; q++) {  // mask convert + STS + popcount
            float4 v0 = ra[2 * q], v1 = ra[2 * q + 1];
            cnt += (v0.x == -1.f) + (v0.y == -1.f) + (v0.z == -1.f) + (v0.w == -1.f)
                 + (v1.x == -1.f) + (v1.y == -1.f) + (v1.z == -1.f) + (v1.w == -1.f);
            uint4 w;
            w.x = (v0.x == -1.f ? 0x3F80u : 0u) | (v0.y == -1.f ? 0x3F800000u : 0u);
            w.y = (v0.z == -1.f ? 0x3F80u : 0u) | (v0.w == -1.f ? 0x3F800000u : 0u);
            w.z = (v1.x == -1.f ? 0x3F80u : 0u) | (v1.y == -1.f ? 0x3F800000u : 0u);
            w.w = (v1.z == -1.f ? 0x3F80u : 0u) | (v1.w == -1.f ? 0x3F800000u : 0u);
            sts128(aB + SWZ((uint32_t)(r * 128 + h * 64 + q * 16)), w);
        }
        if (s < 31) {  // prefetch stage s+1
            uint32_t nb = (uint32_t)(buf ^ 1);
            uint32_t hB2 = tb + 32768u + nb * 16384u;
            uint32_t lB2 = tb + 65536u + nb * 16384u;
            size_t koff = (size_t)(s + 1) * 64;
#pragma unroll
            for (int i = 0; i < 4; i++) {
                int c = t + i * 256, row = c >> 3, j = c & 7;
                uint32_t d = SWZ((uint32_t)(row * 128 + j * 16));
                CP16(hB2 + d, YhG + ((size_t)row * N_ + koff + j * 8) * 2);
                CP16(lB2 + d, YlG + ((size_t)row * N_ + koff + j * 8) * 2);
            }
            CP_COMMIT();
            ap += 64;
#pragma unroll
            for (int q = 0; q < 8; q++) ra[q] = *(const float4*)(ap + q * 4);
            CP_WAIT1();  // stage-s Y arrived (s+1 group may remain in flight)
        } else {
            CP_WAIT0();
        }
        __syncthreads();  // mask STS + Y_s visible to all warps

#pragma unroll
        for (int k = 0; k < 4; k++) {  // 4 x k16
            uint32_t kboff = (uint32_t)((k * 2 + kb0) * 16);
            uint32_t a_[4][4];
#pragma unroll
            for (int mt = 0; mt < 4; mt++) {
                uint32_t row = (uint32_t)(warpM * 64 + mt * 16) + r16;
                LDSM_X4(a_[mt][0], a_[mt][1], a_[mt][2], a_[mt][3],
                        aB + SWZ(row * 128 + kboff));
            }
            uint32_t bh[2][4], bl[2][4];
#pragma unroll
            for (int g = 0; g < 2; g++) {
                uint32_t row = (uint32_t)(warpN * 32 + g * 16) + r16;
                uint32_t off = SWZ(row * 128 + kboff);
                LDSM_X4(bh[g][0], bh[g][1], bh[g][2], bh[g][3], hB + off);
                LDSM_X4(bl[g][0], bl[g][1], bl[g][2], bl[g][3], lB + off);
            }
#pragma unroll
            for (int mt = 0; mt < 4; mt++)
#pragma unroll
                for (int g = 0; g < 2; g++) {
                    MMA_BF16(acc[mt][2 * g],     a_[mt], bh[g][0], bh[g][2]);
                    MMA_BF16(acc[mt][2 * g],     a_[mt], bl[g][0], bl[g][2]);
                    MMA_BF16(acc[mt][2 * g + 1], a_[mt], bh[g][1], bh[g][3]);
                    MMA_BF16(acc[mt][2 * g + 1], a_[mt], bl[g][1], bl[g][3]);
                }
        }
    }

    int oc = __shfl_xor_sync(0xFFFFFFFFu, cnt, 1);
    if (h == 0) { int c2 = cnt + oc; sNorm[r] = (float)(c2 ? c2 : 1); }
    __syncthreads();

#pragma unroll
    for (int mt = 0; mt < 4; mt++) {
        int lr = warpM * 64 + mt * 16 + (lid >> 2);
        float i0 = 1.0f / sNorm[lr];
        float i1 = 1.0f / sNorm[lr + 8];
        float* o0 = out + ((size_t)(b * E_ + e0 + lr)) * F_;
        float* o1 = o0 + 8 * F_;
#pragma unroll
        for (int nt = 0; nt < 4; nt++) {
            int col = warpN * 32 + nt * 8 + (lid & 3) * 2;
            float2 bb = *(const float2*)(bias + col);
            float* d = acc[mt][nt];
            float2 v0, v1;
            v0.x = fmaxf(fmaf(d[0], i0, bb.x), 0.f);
            v0.y = fmaxf(fmaf(d[1], i0, bb.y), 0.f);
            v1.x = fmaxf(fmaf(d[2], i1, bb.x), 0.f);
            v1.y = fmaxf(fmaf(d[3], i1, bb.y), 0.f);
            *(float2*)(o0 + col) = v0;
            *(float2*)(o1 + col) = v1;
        }
    }
}

extern "C" void kernel_launch(void* const* d_in, const int* in_sizes, int n_in,
                              void* d_out, int out_size) {
    const float* X    = (const float*)d_in[0];  // [B,N,F]
    const float* adj  = (const float*)d_in[1];  // [B,E,N]
    const float* W    = (const float*)d_in[2];  // [F,F]
    const float* bias = (const float*)d_in[3];  // [F]
    float* out = (float*)d_out;                 // [B,E,F]
    (void)in_sizes; (void)n_in; (void)out_size;

    const int smem_pro  = (128 * STRX + 128 * STRW) * 4;   // 102400
    const int smem_main = 512 + 1024 + 6 * 16384;          // 99840
    cudaFuncSetAttribute(v2h_prologue, cudaFuncAttributeMaxDynamicSharedMemorySize, smem_pro);
    cudaFuncSetAttribute(v2h_main,     cudaFuncAttributeMaxDynamicSharedMemorySize, smem_main);

    v2h_prologue<<<256, 256, smem_pro>>>(X, W);
    v2h_main<<<128, 256, smem_main>>>(adj, bias, out);
}

// round 10
// speedup vs baseline: 1.1684x; 1.1684x over previous
#include <cuda_runtime.h>
#include <cuda_fp16.h>
#include <cstdint>

#define B_ 8
#define E_ 2048
#define N_ 2048
#define F_ 128

// Y = X @ W^T stored transposed [b][f][n], single fp16 (device scratch).
__device__ __align__(16) __half g_Y[B_ * F_ * N_];

extern __shared__ __align__(16) char g_smem[];

// ---------------- helpers (plain sm_103 features only) ----------------
__device__ __forceinline__ uint32_t smem_u32(const void* p) {
    uint32_t a;
    asm("{ .reg .u64 t; cvta.to.shared.u64 t, %1; cvt.u32.u64 %0, t; }" : "=r"(a) : "l"(p));
    return a;
}
__device__ __forceinline__ uint32_t h2_as_u32(__half2 h) {
    uint32_t u;
    asm("mov.b32 %0, %1;" : "=r"(u) : "r"(*(uint32_t*)&h));
    return u;
}
#define SWZ(x) ((x) ^ (((x) >> 3) & 0x70))

#define CP16(dst, src) \
    asm volatile("cp.async.ca.shared.global [%0], [%1], 16;" :: "r"(dst), "l"(src))
#define CP_COMMIT() asm volatile("cp.async.commit_group;" ::: "memory")
#define CP_WAIT1()  asm volatile("cp.async.wait_group 1;" ::: "memory")
#define CP_WAIT0()  asm volatile("cp.async.wait_group 0;" ::: "memory")

#define LDSM_X4(r0, r1, r2, r3, addr) \
    asm volatile("ldmatrix.sync.aligned.m8n8.x4.shared.b16 {%0,%1,%2,%3}, [%4];" \
                 : "=r"(r0), "=r"(r1), "=r"(r2), "=r"(r3) : "r"(addr))

#define MMA_F16(d, a, b0, b1) \
    asm volatile("mma.sync.aligned.m16n8k16.row.col.f32.f16.f16.f32 " \
                 "{%0,%1,%2,%3}, {%4,%5,%6,%7}, {%8,%9}, {%0,%1,%2,%3};" \
                 : "+f"((d)[0]), "+f"((d)[1]), "+f"((d)[2]), "+f"((d)[3]) \
                 : "r"((a)[0]), "r"((a)[1]), "r"((a)[2]), "r"((a)[3]), \
                   "r"(b0), "r"(b1))

__device__ __forceinline__ void sts128(uint32_t a, uint4 v) {
    asm volatile("st.shared.v4.b32 [%0], {%1, %2, %3, %4};"
                 :: "r"(a), "r"(v.x), "r"(v.y), "r"(v.z), "r"(v.w));
}

// ---------------- Prologue: Y = X @ W^T, fp16, transposed store ----------------
// 128 CTAs (8 b x 16 n-tiles of 128), 256 thr, per-thread 8n x 8f, k in 2 chunks of 64.
#define PSTR 136
__global__ void __launch_bounds__(256) v2h_prologue(const float* __restrict__ X,
                                                    const float* __restrict__ W) {
    float* sXT = (float*)g_smem;           // [64 k][PSTR] (n in cols)
    float* sWT = sXT + 64 * PSTR;          // [64 k][PSTR] (f in cols)
    int t = threadIdx.x;
    int b = blockIdx.x >> 4, n0 = (blockIdx.x & 15) << 7;
    int row = t & 127, half = t >> 7;      // each thread: one X row-half + one W row-half
    int tn = t & 15, tf = t >> 4;

    float acc[8][8];
#pragma unroll
    for (int i = 0; i < 8; i++)
#pragma unroll
        for (int j = 0; j < 8; j++) acc[i][j] = 0.f;

#pragma unroll
    for (int chunk = 0; chunk < 2; chunk++) {
        int k0 = chunk * 64;
        if (chunk) __syncthreads();        // previous chunk fully consumed
        const float* xp = X + ((size_t)(b * N_ + n0 + row)) * F_ + k0 + half * 32;
        const float* wp = W + (size_t)row * F_ + k0 + half * 32;
#pragma unroll
        for (int q = 0; q < 8; q++) {
            float4 xv = *(const float4*)(xp + q * 4);
            float4 wv = *(const float4*)(wp + q * 4);
            int k = half * 32 + q * 4;
            sXT[(k + 0) * PSTR + row] = xv.x; sXT[(k + 1) * PSTR + row] = xv.y;
            sXT[(k + 2) * PSTR + row] = xv.z; sXT[(k + 3) * PSTR + row] = xv.w;
            sWT[(k + 0) * PSTR + row] = wv.x; sWT[(k + 1) * PSTR + row] = wv.y;
            sWT[(k + 2) * PSTR + row] = wv.z; sWT[(k + 3) * PSTR + row] = wv.w;
        }
        __syncthreads();
#pragma unroll 4
        for (int k = 0; k < 64; k++) {
            float4 x0 = *(const float4*)&sXT[k * PSTR + tn * 8];
            float4 x1 = *(const float4*)&sXT[k * PSTR + tn * 8 + 4];
            float4 w0 = *(const float4*)&sWT[k * PSTR + tf * 8];
            float4 w1 = *(const float4*)&sWT[k * PSTR + tf * 8 + 4];
            float xr[8] = {x0.x, x0.y, x0.z, x0.w, x1.x, x1.y, x1.z, x1.w};
            float wr[8] = {w0.x, w0.y, w0.z, w0.w, w1.x, w1.y, w1.z, w1.w};
#pragma unroll
            for (int i = 0; i < 8; i++)
#pragma unroll
                for (int j = 0; j < 8; j++) acc[i][j] = fmaf(xr[i], wr[j], acc[i][j]);
        }
    }
    // store fp16, transposed: Y[b][f][n]
#pragma unroll
    for (int j = 0; j < 8; j++) {
        uint4 u;
        u.x = h2_as_u32(__floats2half2_rn(acc[0][j], acc[1][j]));
        u.y = h2_as_u32(__floats2half2_rn(acc[2][j], acc[3][j]));
        u.z = h2_as_u32(__floats2half2_rn(acc[4][j], acc[5][j]));
        u.w = h2_as_u32(__floats2half2_rn(acc[6][j], acc[7][j]));
        *(uint4*)(g_Y + ((size_t)(b * F_ + tf * 8 + j)) * N_ + n0 + tn * 8) = u;
    }
}

// ---------------- Main: out = relu((mask @ Y)/norm + b) via mma.sync fp16 ----------------
// grid 128 = b*16 + etile; 256 thr = 8 warps (2M x 4N), warp tile 64x32.
// 32 stages of K=64; A(mask) LDG->STS, Y cp.async; double-buffered smem.
__global__ void __launch_bounds__(256, 1) v2h_main(const float* __restrict__ adj,
                                                   const float* __restrict__ bias,
                                                   float* __restrict__ out) {
    uint32_t sb = smem_u32(g_smem);
    float* sNorm = (float*)g_smem;                       // 128 floats
    const uint32_t tb = (sb + 512u + 1023u) & ~1023u;    // 1024B-aligned tiles
    int t = threadIdx.x, lid = t & 31, wid = t >> 5;
    int warpM = wid >> 2, warpN = wid & 3;               // 2 x 4
    int b = blockIdx.x >> 4, e0 = (blockIdx.x & 15) << 7;

    int r = t >> 1, h = t & 1;                            // conversion mapping
    const float* ap = adj + ((size_t)(b * E_ + e0 + r)) * N_ + h * 32;
    const char* YG = (const char*)(g_Y + (size_t)b * F_ * N_);

    // prefetch stage 0: adj regs + Y cp.async
    float4 ra[8];
#pragma unroll
    for (int q = 0; q < 8; q++) ra[q] = *(const float4*)(ap + q * 4);
    {
        uint32_t yB0 = tb + 32768u;
#pragma unroll
        for (int i = 0; i < 4; i++) {
            int c = t + i * 256, rw = c >> 3, j = c & 7;
            CP16(yB0 + SWZ((uint32_t)(rw * 128 + j * 16)),
                 YG + ((size_t)rw * N_ + j * 8) * 2);
        }
        CP_COMMIT();
    }

    float acc[4][4][4];
#pragma unroll
    for (int m = 0; m < 4; m++)
#pragma unroll
        for (int n = 0; n < 4; n++)
#pragma unroll
            for (int v = 0; v < 4; v++) acc[m][n][v] = 0.f;
    int cnt = 0;
    const uint32_t r16 = (uint32_t)(lid & 15), kb0 = (uint32_t)(lid >> 4);

    for (int s = 0; s < 32; s++) {
        int buf = s & 1;
        uint32_t aB = tb + buf * 16384u;
        uint32_t yB = tb + 32768u + buf * 16384u;
        __syncthreads();  // bufA[s%2] and Y buf (s+1)%2 free (readers of s-1 done)
#pragma unroll
        for (int q = 0; q < 4; q++) {  // mask convert (fp16 1.0 = 0x3C00) + STS + popcount
            float4 v0 = ra[2 * q], v1 = ra[2 * q + 1];
            cnt += (v0.x == -1.f) + (v0.y == -1.f) + (v0.z == -1.f) + (v0.w == -1.f)
                 + (v1.x == -1.f) + (v1.y == -1.f) + (v1.z == -1.f) + (v1.w == -1.f);
            uint4 w;
            w.x = (v0.x == -1.f ? 0x3C00u : 0u) | (v0.y == -1.f ? 0x3C000000u : 0u);
            w.y = (v0.z == -1.f ? 0x3C00u : 0u) | (v0.w == -1.f ? 0x3C000000u : 0u);
            w.z = (v1.x == -1.f ? 0x3C00u : 0u) | (v1.y == -1.f ? 0x3C000000u : 0u);
            w.w = (v1.z == -1.f ? 0x3C00u : 0u) | (v1.w == -1.f ? 0x3C000000u : 0u);
            sts128(aB + SWZ((uint32_t)(r * 128 + h * 64 + q * 16)), w);
        }
        if (s < 31) {  // prefetch stage s+1
            uint32_t yB2 = tb + 32768u + (uint32_t)(buf ^ 1) * 16384u;
            size_t koff = (size_t)(s + 1) * 64;
#pragma unroll
            for (int i = 0; i < 4; i++) {
                int c = t + i * 256, rw = c >> 3, j = c & 7;
                CP16(yB2 + SWZ((uint32_t)(rw * 128 + j * 16)),
                     YG + ((size_t)rw * N_ + koff + j * 8) * 2);
            }
            CP_COMMIT();
            ap += 64;
#pragma unroll
            for (int q = 0; q < 8; q++) ra[q] = *(const float4*)(ap + q * 4);
            CP_WAIT1();  // stage-s Y arrived (s+1 group may remain in flight)
        } else {
            CP_WAIT0();
        }
        __syncthreads();  // mask STS + Y_s visible to all warps

#pragma unroll
        for (int k = 0; k < 4; k++) {  // 4 x k16
            uint32_t kboff = (uint32_t)((k * 2 + kb0) * 16);
            uint32_t a_[4][4];
#pragma unroll
            for (int mt = 0; mt < 4; mt++) {
                uint32_t row = (uint32_t)(warpM * 64 + mt * 16) + r16;
                LDSM_X4(a_[mt][0], a_[mt][1], a_[mt][2], a_[mt][3],
                        aB + SWZ(row * 128 + kboff));
            }
            uint32_t bh[2][4];
#pragma unroll
            for (int g = 0; g < 2; g++) {
                uint32_t row = (uint32_t)(warpN * 32 + g * 16) + r16;
                LDSM_X4(bh[g][0], bh[g][1], bh[g][2], bh[g][3],
                        yB + SWZ(row * 128 + kboff));
            }
#pragma unroll
            for (int mt = 0; mt < 4; mt++)
#pragma unroll
                for (int g = 0; g < 2; g++) {
                    MMA_F16(acc[mt][2 * g],     a_[mt], bh[g][0], bh[g][2]);
                    MMA_F16(acc[mt][2 * g + 1], a_[mt], bh[g][1], bh[g][3]);
                }
        }
    }

    int oc = __shfl_xor_sync(0xFFFFFFFFu, cnt, 1);
    if (h == 0) { int c2 = cnt + oc; sNorm[r] = (float)(c2 ? c2 : 1); }
    __syncthreads();

#pragma unroll
    for (int mt = 0; mt < 4; mt++) {
        int lr = warpM * 64 + mt * 16 + (lid >> 2);
        float i0 = 1.0f / sNorm[lr];
        float i1 = 1.0f / sNorm[lr + 8];
        float* o0 = out + ((size_t)(b * E_ + e0 + lr)) * F_;
        float* o1 = o0 + 8 * F_;
#pragma unroll
        for (int nt = 0; nt < 4; nt++) {
            int col = warpN * 32 + nt * 8 + (lid & 3) * 2;
            float2 bb = *(const float2*)(bias + col);
            float* d = acc[mt][nt];
            float2 v0, v1;
            v0.x = fmaxf(fmaf(d[0], i0, bb.x), 0.f);
            v0.y = fmaxf(fmaf(d[1], i0, bb.y), 0.f);
            v1.x = fmaxf(fmaf(d[2], i1, bb.x), 0.f);
            v1.y = fmaxf(fmaf(d[3], i1, bb.y), 0.f);
            *(float2*)(o0 + col) = v0;
            *(float2*)(o1 + col) = v1;
        }
    }
}

extern "C" void kernel_launch(void* const* d_in, const int* in_sizes, int n_in,
                              void* d_out, int out_size) {
    const float* X    = (const float*)d_in[0];  // [B,N,F]
    const float* adj  = (const float*)d_in[1];  // [B,E,N]
    const float* W    = (const float*)d_in[2];  // [F,F]
    const float* bias = (const float*)d_in[3];  // [F]
    float* out = (float*)d_out;                 // [B,E,F]
    (void)in_sizes; (void)n_in; (void)out_size;

    const int smem_pro  = 2 * 64 * PSTR * 4;               // 69632
    const int smem_main = 512 + 1024 + 4 * 16384;          // 67072
    cudaFuncSetAttribute(v2h_prologue, cudaFuncAttributeMaxDynamicSharedMemorySize, smem_pro);
    cudaFuncSetAttribute(v2h_main,     cudaFuncAttributeMaxDynamicSharedMemorySize, smem_main);

    v2h_prologue<<<128, 256, smem_pro>>>(X, W);
    v2h_main<<<128, 256, smem_main>>>(adj, bias, out);
}

// round 11
// speedup vs baseline: 1.1986x; 1.0258x over previous
#include <cuda_runtime.h>
#include <cuda_fp16.h>
#include <cstdint>

#define B_ 8
#define E_ 2048
#define N_ 2048
#define F_ 128

// Y = X @ W^T stored transposed [b][f][n], single fp16 (device scratch).
__device__ __align__(16) __half g_Y[B_ * F_ * N_];

extern __shared__ __align__(16) char g_smem[];

// ---------------- helpers (plain sm_103 features only) ----------------
__device__ __forceinline__ uint32_t smem_u32(const void* p) {
    uint32_t a;
    asm("{ .reg .u64 t; cvta.to.shared.u64 t, %1; cvt.u32.u64 %0, t; }" : "=r"(a) : "l"(p));
    return a;
}
__device__ __forceinline__ uint32_t h2_as_u32(__half2 h) {
    uint32_t u;
    asm("mov.b32 %0, %1;" : "=r"(u) : "r"(*(uint32_t*)&h));
    return u;
}
#define SWZ(x) ((x) ^ (((x) >> 3) & 0x70))

#define CP16(dst, src) \
    asm volatile("cp.async.ca.shared.global [%0], [%1], 16;" :: "r"(dst), "l"(src))
#define CP_COMMIT() asm volatile("cp.async.commit_group;" ::: "memory")
#define CP_WAIT1()  asm volatile("cp.async.wait_group 1;" ::: "memory")
#define CP_WAIT0()  asm volatile("cp.async.wait_group 0;" ::: "memory")

#define LDSM_X4(r0, r1, r2, r3, addr) \
    asm volatile("ldmatrix.sync.aligned.m8n8.x4.shared.b16 {%0,%1,%2,%3}, [%4];" \
                 : "=r"(r0), "=r"(r1), "=r"(r2), "=r"(r3) : "r"(addr))

#define MMA_F16(d, a, b0, b1) \
    asm volatile("mma.sync.aligned.m16n8k16.row.col.f32.f16.f16.f32 " \
                 "{%0,%1,%2,%3}, {%4,%5,%6,%7}, {%8,%9}, {%0,%1,%2,%3};" \
                 : "+f"((d)[0]), "+f"((d)[1]), "+f"((d)[2]), "+f"((d)[3]) \
                 : "r"((a)[0]), "r"((a)[1]), "r"((a)[2]), "r"((a)[3]), \
                   "r"(b0), "r"(b1))

__device__ __forceinline__ float2 lds64(uint32_t a) {
    float2 v;
    asm("ld.shared.v2.f32 {%0,%1}, [%2];" : "=f"(v.x), "=f"(v.y) : "r"(a));
    return v;
}
__device__ __forceinline__ uint32_t mask2(float2 v) {
    return (v.x == -1.f ? 0x3C00u : 0u) | (v.y == -1.f ? 0x3C000000u : 0u);
}

// ---------------- Prologue: Y = X @ W^T, fp16, transposed store ----------------
// 128 CTAs (8 b x 16 n-tiles of 128), 256 thr, per-thread 8n x 8f, k in 2 chunks of 64.
#define PSTR 136
__global__ void __launch_bounds__(256) v2h_prologue(const float* __restrict__ X,
                                                    const float* __restrict__ W) {
    float* sXT = (float*)g_smem;           // [64 k][PSTR] (n in cols)
    float* sWT = sXT + 64 * PSTR;          // [64 k][PSTR] (f in cols)
    int t = threadIdx.x;
    int b = blockIdx.x >> 4, n0 = (blockIdx.x & 15) << 7;
    int row = t & 127, half = t >> 7;
    int tn = t & 15, tf = t >> 4;

    float acc[8][8];
#pragma unroll
    for (int i = 0; i < 8; i++)
#pragma unroll
        for (int j = 0; j < 8; j++) acc[i][j] = 0.f;

#pragma unroll
    for (int chunk = 0; chunk < 2; chunk++) {
        int k0 = chunk * 64;
        if (chunk) __syncthreads();
        const float* xp = X + ((size_t)(b * N_ + n0 + row)) * F_ + k0 + half * 32;
        const float* wp = W + (size_t)row * F_ + k0 + half * 32;
#pragma unroll
        for (int q = 0; q < 8; q++) {
            float4 xv = *(const float4*)(xp + q * 4);
            float4 wv = *(const float4*)(wp + q * 4);
            int k = half * 32 + q * 4;
            sXT[(k + 0) * PSTR + row] = xv.x; sXT[(k + 1) * PSTR + row] = xv.y;
            sXT[(k + 2) * PSTR + row] = xv.z; sXT[(k + 3) * PSTR + row] = xv.w;
            sWT[(k + 0) * PSTR + row] = wv.x; sWT[(k + 1) * PSTR + row] = wv.y;
            sWT[(k + 2) * PSTR + row] = wv.z; sWT[(k + 3) * PSTR + row] = wv.w;
        }
        __syncthreads();
#pragma unroll 4
        for (int k = 0; k < 64; k++) {
            float4 x0 = *(const float4*)&sXT[k * PSTR + tn * 8];
            float4 x1 = *(const float4*)&sXT[k * PSTR + tn * 8 + 4];
            float4 w0 = *(const float4*)&sWT[k * PSTR + tf * 8];
            float4 w1 = *(const float4*)&sWT[k * PSTR + tf * 8 + 4];
            float xr[8] = {x0.x, x0.y, x0.z, x0.w, x1.x, x1.y, x1.z, x1.w};
            float wr[8] = {w0.x, w0.y, w0.z, w0.w, w1.x, w1.y, w1.z, w1.w};
#pragma unroll
            for (int i = 0; i < 8; i++)
#pragma unroll
                for (int j = 0; j < 8; j++) acc[i][j] = fmaf(xr[i], wr[j], acc[i][j]);
        }
    }
#pragma unroll
    for (int j = 0; j < 8; j++) {
        uint4 u;
        u.x = h2_as_u32(__floats2half2_rn(acc[0][j], acc[1][j]));
        u.y = h2_as_u32(__floats2half2_rn(acc[2][j], acc[3][j]));
        u.z = h2_as_u32(__floats2half2_rn(acc[4][j], acc[5][j]));
        u.w = h2_as_u32(__floats2half2_rn(acc[6][j], acc[7][j]));
        *(uint4*)(g_Y + ((size_t)(b * F_ + tf * 8 + j)) * N_ + n0 + tn * 8) = u;
    }
}

// ---------------- Main: out = relu((mask @ Y)/norm + b), fully async inputs ----------------
// grid 128 = b*16 + etile; 256 thr = 8 warps (2M x 4N), warp tile 64x32.
// 32 stages of K=64. adj fp32 AND Y fp16 via cp.async (double-buffered).
// Mask fragments built from fp32 smem during compute (overlaps HMMA); popcount rides along.
// adj tile layout: [128 rows][64 floats], row stride 256B, 16B chunk c stored at (c ^ (row&7)).
__global__ void __launch_bounds__(256, 1) v2h_main(const float* __restrict__ adj,
                                                   const float* __restrict__ bias,
                                                   float* __restrict__ out) {
    uint32_t sb = smem_u32(g_smem);
    float* sNorm = (float*)g_smem;                       // 128 floats
    const uint32_t tb = (sb + 512u + 1023u) & ~1023u;
    int t = threadIdx.x, lid = t & 31, wid = t >> 5;
    int warpM = wid >> 2, warpN = wid & 3;               // 2 x 4
    int b = blockIdx.x >> 4, e0 = (blockIdx.x & 15) << 7;

    const char* adjB = (const char*)(adj + ((size_t)(b * E_ + e0)) * N_);
    const char* YG   = (const char*)(g_Y + (size_t)b * F_ * N_);

    // prefetch stage 0 (group G0)
    {
        uint32_t aB0 = tb, yB0 = tb + 65536u;
#pragma unroll
        for (int i = 0; i < 8; i++) {
            uint32_t cid = (uint32_t)(t + i * 256), row = cid >> 4, c = cid & 15;
            CP16(aB0 + row * 256u + ((c ^ (row & 7u)) << 4),
                 adjB + (size_t)row * (N_ * 4) + c * 16);
        }
#pragma unroll
        for (int i = 0; i < 4; i++) {
            int cid = t + i * 256, rw = cid >> 3, j = cid & 7;
            CP16(yB0 + SWZ((uint32_t)(rw * 128 + j * 16)),
                 YG + ((size_t)rw * N_ + j * 8) * 2);
        }
        CP_COMMIT();
    }

    float acc[4][4][4];
#pragma unroll
    for (int m = 0; m < 4; m++)
#pragma unroll
        for (int n = 0; n < 4; n++)
#pragma unroll
            for (int v = 0; v < 4; v++) acc[m][n][v] = 0.f;
    int cnt[4][2];
#pragma unroll
    for (int m = 0; m < 4; m++) { cnt[m][0] = 0; cnt[m][1] = 0; }

    const uint32_t r16 = (uint32_t)(lid & 15), kb0 = (uint32_t)(lid >> 4);
    const uint32_t qrow = (uint32_t)(lid >> 2), qk = (uint32_t)(lid & 3);
    const uint32_t boff = (uint32_t)((lid & 1) * 8);

    for (int s = 0; s < 32; s++) {
        int buf = s & 1;
        uint32_t aB = tb + (uint32_t)buf * 32768u;
        uint32_t yB = tb + 65536u + (uint32_t)buf * 16384u;
        __syncthreads();  // all warps done reading buf^1 (stage s-1) -> safe to refill
        if (s < 31) {
            uint32_t aB2 = tb + (uint32_t)(buf ^ 1) * 32768u;
            uint32_t yB2 = tb + 65536u + (uint32_t)(buf ^ 1) * 16384u;
            const char* adjS = adjB + (size_t)(s + 1) * 256;
            size_t koff = (size_t)(s + 1) * 64;
#pragma unroll
            for (int i = 0; i < 8; i++) {
                uint32_t cid = (uint32_t)(t + i * 256), row = cid >> 4, c = cid & 15;
                CP16(aB2 + row * 256u + ((c ^ (row & 7u)) << 4),
                     adjS + (size_t)row * (N_ * 4) + c * 16);
            }
#pragma unroll
            for (int i = 0; i < 4; i++) {
                int cid = t + i * 256, rw = cid >> 3, j = cid & 7;
                CP16(yB2 + SWZ((uint32_t)(rw * 128 + j * 16)),
                     YG + ((size_t)rw * N_ + koff + j * 8) * 2);
            }
            CP_COMMIT();
            CP_WAIT1();   // group for stage s complete (s+1 still in flight)
        } else {
            CP_WAIT0();
        }
        __syncthreads();  // stage-s smem visible to all warps

#pragma unroll
        for (int kb = 0; kb < 4; kb++) {
            uint32_t c0 = (uint32_t)kb * 4 + (qk >> 1);
            uint32_t bh[2][4];
#pragma unroll
            for (int g = 0; g < 2; g++) {
                uint32_t row = (uint32_t)(warpN * 32 + g * 16) + r16;
                LDSM_X4(bh[g][0], bh[g][1], bh[g][2], bh[g][3],
                        yB + SWZ(row * 128 + ((uint32_t)kb * 2 + kb0) * 16));
            }
#pragma unroll
            for (int mt = 0; mt < 4; mt++) {
                uint32_t r0 = (uint32_t)(warpM * 64 + mt * 16) + qrow;
                uint32_t b0a = aB + r0 * 256u;
                uint32_t b1a = b0a + 8u * 256u;
                uint32_t x7 = (r0 & 7u);  // (r0+8)&7 == r0&7
                float2 lo0 = lds64(b0a + ((c0 ^ x7) << 4) + boff);
                float2 lo1 = lds64(b1a + ((c0 ^ x7) << 4) + boff);
                float2 hi0 = lds64(b0a + (((c0 + 2u) ^ x7) << 4) + boff);
                float2 hi1 = lds64(b1a + (((c0 + 2u) ^ x7) << 4) + boff);
                uint32_t a_[4] = { mask2(lo0), mask2(lo1), mask2(hi0), mask2(hi1) };
                if (warpN == 0) {
                    cnt[mt][0] += (lo0.x == -1.f) + (lo0.y == -1.f)
                                + (hi0.x == -1.f) + (hi0.y == -1.f);
                    cnt[mt][1] += (lo1.x == -1.f) + (lo1.y == -1.f)
                                + (hi1.x == -1.f) + (hi1.y == -1.f);
                }
                MMA_F16(acc[mt][0], a_, bh[0][0], bh[0][2]);
                MMA_F16(acc[mt][1], a_, bh[0][1], bh[0][3]);
                MMA_F16(acc[mt][2], a_, bh[1][0], bh[1][2]);
                MMA_F16(acc[mt][3], a_, bh[1][1], bh[1][3]);
            }
        }
    }

    // norm: quad-reduce per-row counts (warps 0 and 4 hold complete rows)
    if (warpN == 0) {
#pragma unroll
        for (int mt = 0; mt < 4; mt++)
#pragma unroll
            for (int j = 0; j < 2; j++) {
                int c = cnt[mt][j];
                c += __shfl_xor_sync(0xFFFFFFFFu, c, 1);
                c += __shfl_xor_sync(0xFFFFFFFFu, c, 2);
                if ((lid & 3) == 0)
                    sNorm[warpM * 64 + mt * 16 + j * 8 + (lid >> 2)] = (float)(c ? c : 1);
            }
    }
    __syncthreads();

#pragma unroll
    for (int mt = 0; mt < 4; mt++) {
        int lr = warpM * 64 + mt * 16 + (lid >> 2);
        float i0 = 1.0f / sNorm[lr];
        float i1 = 1.0f / sNorm[lr + 8];
        float* o0 = out + ((size_t)(b * E_ + e0 + lr)) * F_;
        float* o1 = o0 + 8 * F_;
#pragma unroll
        for (int nt = 0; nt < 4; nt++) {
            int col = warpN * 32 + nt * 8 + (lid & 3) * 2;
            float2 bb = *(const float2*)(bias + col);
            float* d = acc[mt][nt];
            float2 v0, v1;
            v0.x = fmaxf(fmaf(d[0], i0, bb.x), 0.f);
            v0.y = fmaxf(fmaf(d[1], i0, bb.y), 0.f);
            v1.x = fmaxf(fmaf(d[2], i1, bb.x), 0.f);
            v1.y = fmaxf(fmaf(d[3], i1, bb.y), 0.f);
            *(float2*)(o0 + col) = v0;
            *(float2*)(o1 + col) = v1;
        }
    }
}

extern "C" void kernel_launch(void* const* d_in, const int* in_sizes, int n_in,
                              void* d_out, int out_size) {
    const float* X    = (const float*)d_in[0];  // [B,N,F]
    const float* adj  = (const float*)d_in[1];  // [B,E,N]
    const float* W    = (const float*)d_in[2];  // [F,F]
    const float* bias = (const float*)d_in[3];  // [F]
    float* out = (float*)d_out;                 // [B,E,F]
    (void)in_sizes; (void)n_in; (void)out_size;

    const int smem_pro  = 2 * 64 * PSTR * 4;               // 69632
    const int smem_main = 512 + 1024 + 2 * 32768 + 2 * 16384;  // 99840
    cudaFuncSetAttribute(v2h_prologue, cudaFuncAttributeMaxDynamicSharedMemorySize, smem_pro);
    cudaFuncSetAttribute(v2h_main,     cudaFuncAttributeMaxDynamicSharedMemorySize, smem_main);

    v2h_prologue<<<128, 256, smem_pro>>>(X, W);
    v2h_main<<<128, 256, smem_main>>>(adj, bias, out);
}

// round 12
// speedup vs baseline: 1.6116x; 1.3446x over previous
#include <cuda_runtime.h>
#include <cuda_fp16.h>
#include <cstdint>

#define B_ 8
#define E_ 2048
#define N_ 2048
#define F_ 128

// Y = X @ W^T stored transposed [b][f][n], single fp16 (device scratch).
__device__ __align__(16) __half g_Y[B_ * F_ * N_];

extern __shared__ __align__(16) char g_smem[];

// ---------------- helpers ----------------
__device__ __forceinline__ uint32_t smem_u32(const void* p) {
    uint32_t a;
    asm("{ .reg .u64 t; cvta.to.shared.u64 t, %1; cvt.u32.u64 %0, t; }" : "=r"(a) : "l"(p));
    return a;
}
__device__ __forceinline__ uint32_t h2_as_u32(__half2 h) {
    uint32_t u;
    asm("mov.b32 %0, %1;" : "=r"(u) : "r"(*(uint32_t*)&h));
    return u;
}
#define SWZ(x) ((x) ^ (((x) >> 3) & 0x70))

#define CP16(dst, src) \
    asm volatile("cp.async.ca.shared.global [%0], [%1], 16;" :: "r"(dst), "l"(src))
#define CP_COMMIT() asm volatile("cp.async.commit_group;" ::: "memory")
#define CP_WAIT1()  asm volatile("cp.async.wait_group 1;" ::: "memory")
#define CP_WAIT0()  asm volatile("cp.async.wait_group 0;" ::: "memory")

#define LDSM_X4(r0, r1, r2, r3, addr) \
    asm volatile("ldmatrix.sync.aligned.m8n8.x4.shared.b16 {%0,%1,%2,%3}, [%4];" \
                 : "=r"(r0), "=r"(r1), "=r"(r2), "=r"(r3) : "r"(addr))

#define MMA_F16(d, a, b0, b1) \
    asm volatile("mma.sync.aligned.m16n8k16.row.col.f32.f16.f16.f32 " \
                 "{%0,%1,%2,%3}, {%4,%5,%6,%7}, {%8,%9}, {%0,%1,%2,%3};" \
                 : "+f"((d)[0]), "+f"((d)[1]), "+f"((d)[2]), "+f"((d)[3]) \
                 : "r"((a)[0]), "r"((a)[1]), "r"((a)[2]), "r"((a)[3]), \
                   "r"(b0), "r"(b1))

__device__ __forceinline__ void sts128(uint32_t a, uint4 v) {
    asm volatile("st.shared.v4.b32 [%0], {%1, %2, %3, %4};"
                 :: "r"(a), "r"(v.x), "r"(v.y), "r"(v.z), "r"(v.w));
}
__device__ __forceinline__ uint32_t mask2(float x, float y) {
    return (x == -1.f ? 0x3C00u : 0u) | (y == -1.f ? 0x3C000000u : 0u);
}

// ---------------- Prologue: Y = X @ W^T, fp16, transposed store (unchanged) ----------------
#define PSTR 136
__global__ void __launch_bounds__(256) v2h_prologue(const float* __restrict__ X,
                                                    const float* __restrict__ W) {
    float* sXT = (float*)g_smem;
    float* sWT = sXT + 64 * PSTR;
    int t = threadIdx.x;
    int b = blockIdx.x >> 4, n0 = (blockIdx.x & 15) << 7;
    int row = t & 127, half = t >> 7;
    int tn = t & 15, tf = t >> 4;

    float acc[8][8];
#pragma unroll
    for (int i = 0; i < 8; i++)
#pragma unroll
        for (int j = 0; j < 8; j++) acc[i][j] = 0.f;

#pragma unroll
    for (int chunk = 0; chunk < 2; chunk++) {
        int k0 = chunk * 64;
        if (chunk) __syncthreads();
        const float* xp = X + ((size_t)(b * N_ + n0 + row)) * F_ + k0 + half * 32;
        const float* wp = W + (size_t)row * F_ + k0 + half * 32;
#pragma unroll
        for (int q = 0; q < 8; q++) {
            float4 xv = *(const float4*)(xp + q * 4);
            float4 wv = *(const float4*)(wp + q * 4);
            int k = half * 32 + q * 4;
            sXT[(k + 0) * PSTR + row] = xv.x; sXT[(k + 1) * PSTR + row] = xv.y;
            sXT[(k + 2) * PSTR + row] = xv.z; sXT[(k + 3) * PSTR + row] = xv.w;
            sWT[(k + 0) * PSTR + row] = wv.x; sWT[(k + 1) * PSTR + row] = wv.y;
            sWT[(k + 2) * PSTR + row] = wv.z; sWT[(k + 3) * PSTR + row] = wv.w;
        }
        __syncthreads();
#pragma unroll 4
        for (int k = 0; k < 64; k++) {
            float4 x0 = *(const float4*)&sXT[k * PSTR + tn * 8];
            float4 x1 = *(const float4*)&sXT[k * PSTR + tn * 8 + 4];
            float4 w0 = *(const float4*)&sWT[k * PSTR + tf * 8];
            float4 w1 = *(const float4*)&sWT[k * PSTR + tf * 8 + 4];
            float xr[8] = {x0.x, x0.y, x0.z, x0.w, x1.x, x1.y, x1.z, x1.w};
            float wr[8] = {w0.x, w0.y, w0.z, w0.w, w1.x, w1.y, w1.z, w1.w};
#pragma unroll
            for (int i = 0; i < 8; i++)
#pragma unroll
                for (int j = 0; j < 8; j++) acc[i][j] = fmaf(xr[i], wr[j], acc[i][j]);
        }
    }
#pragma unroll
    for (int j = 0; j < 8; j++) {
        uint4 u;
        u.x = h2_as_u32(__floats2half2_rn(acc[0][j], acc[1][j]));
        u.y = h2_as_u32(__floats2half2_rn(acc[2][j], acc[3][j]));
        u.z = h2_as_u32(__floats2half2_rn(acc[4][j], acc[5][j]));
        u.w = h2_as_u32(__floats2half2_rn(acc[6][j], acc[7][j]));
        *(uint4*)(g_Y + ((size_t)(b * F_ + tf * 8 + j)) * N_ + n0 + tn * 8) = u;
    }
}

// ---------------- Main: out = relu((mask @ Y)/norm + b) ----------------
// grid 256 = b*32 + etile(64 rows); 256 thr = 8 warps (2M x 4N), warp tile 32x32.
// 2 CTAs/SM (launch_bounds cap 128 regs). 32 stages of K=64.
// adj: LDG->regs (prefetch 1 stage) -> fp16 mask STS. Y: cp.async double-buffered.
__global__ void __launch_bounds__(256, 2) v2h_main(const float* __restrict__ adj,
                                                   const float* __restrict__ bias,
                                                   float* __restrict__ out) {
    uint32_t sb = smem_u32(g_smem);
    float* sNorm = (float*)g_smem;                       // 64 floats
    const uint32_t tb = (sb + 256u + 1023u) & ~1023u;
    int t = threadIdx.x, lid = t & 31, wid = t >> 5;
    int warpM = wid >> 2, warpN = wid & 3;               // 2 x 4
    int b = blockIdx.x >> 5, e0 = (blockIdx.x & 31) << 6;

    int r = t >> 2, seg = t & 3;                          // convert mapping: 4 thr/row, 16k each
    const float* ap = adj + ((size_t)(b * E_ + e0 + r)) * N_ + seg * 16;
    const char* YG = (const char*)(g_Y + (size_t)b * F_ * N_);

    // prefetch stage 0: adj regs + Y cp.async
    float4 ra[4];
#pragma unroll
    for (int q = 0; q < 4; q++) ra[q] = *(const float4*)(ap + q * 4);
    {
        uint32_t yB0 = tb + 16384u;
#pragma unroll
        for (int i = 0; i < 4; i++) {
            int cid = t + i * 256, rw = cid >> 3, j = cid & 7;
            CP16(yB0 + SWZ((uint32_t)(rw * 128 + j * 16)),
                 YG + ((size_t)rw * N_ + j * 8) * 2);
        }
        CP_COMMIT();
    }

    float acc[2][4][4];
#pragma unroll
    for (int m = 0; m < 2; m++)
#pragma unroll
        for (int n = 0; n < 4; n++)
#pragma unroll
            for (int v = 0; v < 4; v++) acc[m][n][v] = 0.f;
    int cnt = 0;
    const uint32_t r16 = (uint32_t)(lid & 15), kb0 = (uint32_t)(lid >> 4);
    const uint32_t stsOff = (uint32_t)(r * 128 + seg * 32);

    for (int s = 0; s < 32; s++) {
        int buf = s & 1;
        uint32_t aB = tb + (uint32_t)buf * 8192u;
        uint32_t yB = tb + 16384u + (uint32_t)buf * 16384u;
        __syncthreads();  // buffers for stage s free (readers of s-1 done)
        {   // mask convert (fp16 1.0 = 0x3C00) + STS + popcount
            float4 v0 = ra[0], v1 = ra[1], v2 = ra[2], v3 = ra[3];
            cnt += (v0.x == -1.f) + (v0.y == -1.f) + (v0.z == -1.f) + (v0.w == -1.f)
                 + (v1.x == -1.f) + (v1.y == -1.f) + (v1.z == -1.f) + (v1.w == -1.f)
                 + (v2.x == -1.f) + (v2.y == -1.f) + (v2.z == -1.f) + (v2.w == -1.f)
                 + (v3.x == -1.f) + (v3.y == -1.f) + (v3.z == -1.f) + (v3.w == -1.f);
            uint4 u0, u1;
            u0.x = mask2(v0.x, v0.y); u0.y = mask2(v0.z, v0.w);
            u0.z = mask2(v1.x, v1.y); u0.w = mask2(v1.z, v1.w);
            u1.x = mask2(v2.x, v2.y); u1.y = mask2(v2.z, v2.w);
            u1.z = mask2(v3.x, v3.y); u1.w = mask2(v3.z, v3.w);
            sts128(aB + SWZ(stsOff), u0);
            sts128(aB + SWZ(stsOff + 16u), u1);
        }
        if (s < 31) {  // prefetch stage s+1
            ap += 64;
#pragma unroll
            for (int q = 0; q < 4; q++) ra[q] = *(const float4*)(ap + q * 4);
            uint32_t yB2 = tb + 16384u + (uint32_t)(buf ^ 1) * 16384u;
            size_t koff = (size_t)(s + 1) * 64;
#pragma unroll
            for (int i = 0; i < 4; i++) {
                int cid = t + i * 256, rw = cid >> 3, j = cid & 7;
                CP16(yB2 + SWZ((uint32_t)(rw * 128 + j * 16)),
                     YG + ((size_t)rw * N_ + koff + j * 8) * 2);
            }
            CP_COMMIT();
            CP_WAIT1();   // Y_s arrived (Y_{s+1} still in flight)
        } else {
            CP_WAIT0();
        }
        __syncthreads();  // mask + Y_s visible

#pragma unroll
        for (int kb = 0; kb < 4; kb++) {
            uint32_t koffb = ((uint32_t)kb * 2 + kb0) * 16;
            uint32_t a_[2][4];
#pragma unroll
            for (int mt = 0; mt < 2; mt++) {
                uint32_t row = (uint32_t)(warpM * 32 + mt * 16) + r16;
                LDSM_X4(a_[mt][0], a_[mt][1], a_[mt][2], a_[mt][3],
                        aB + SWZ(row * 128 + koffb));
            }
            uint32_t bh[2][4];
#pragma unroll
            for (int g = 0; g < 2; g++) {
                uint32_t row = (uint32_t)(warpN * 32 + g * 16) + r16;
                LDSM_X4(bh[g][0], bh[g][1], bh[g][2], bh[g][3],
                        yB + SWZ(row * 128 + koffb));
            }
#pragma unroll
            for (int mt = 0; mt < 2; mt++)
#pragma unroll
                for (int g = 0; g < 2; g++) {
                    MMA_F16(acc[mt][2 * g],     a_[mt], bh[g][0], bh[g][2]);
                    MMA_F16(acc[mt][2 * g + 1], a_[mt], bh[g][1], bh[g][3]);
                }
        }
    }

    // norm: quad-reduce (4 threads per row share r = t>>2)
    {
        int c = cnt;
        c += __shfl_xor_sync(0xFFFFFFFFu, c, 1);
        c += __shfl_xor_sync(0xFFFFFFFFu, c, 2);
        if ((lid & 3) == 0) sNorm[r] = (float)(c ? c : 1);
    }
    __syncthreads();

#pragma unroll
    for (int mt = 0; mt < 2; mt++) {
        int lr = warpM * 32 + mt * 16 + (lid >> 2);
        float i0 = 1.0f / sNorm[lr];
        float i1 = 1.0f / sNorm[lr + 8];
        float* o0 = out + ((size_t)(b * E_ + e0 + lr)) * F_;
        float* o1 = o0 + 8 * F_;
#pragma unroll
        for (int nt = 0; nt < 4; nt++) {
            int col = warpN * 32 + nt * 8 + (lid & 3) * 2;
            float2 bb = *(const float2*)(bias + col);
            float* d = acc[mt][nt];
            float2 v0, v1;
            v0.x = fmaxf(fmaf(d[0], i0, bb.x), 0.f);
            v0.y = fmaxf(fmaf(d[1], i0, bb.y), 0.f);
            v1.x = fmaxf(fmaf(d[2], i1, bb.x), 0.f);
            v1.y = fmaxf(fmaf(d[3], i1, bb.y), 0.f);
            *(float2*)(o0 + col) = v0;
            *(float2*)(o1 + col) = v1;
        }
    }
}

extern "C" void kernel_launch(void* const* d_in, const int* in_sizes, int n_in,
                              void* d_out, int out_size) {
    const float* X    = (const float*)d_in[0];  // [B,N,F]
    const float* adj  = (const float*)d_in[1];  // [B,E,N]
    const float* W    = (const float*)d_in[2];  // [F,F]
    const float* bias = (const float*)d_in[3];  // [F]
    float* out = (float*)d_out;                 // [B,E,F]
    (void)in_sizes; (void)n_in; (void)out_size;

    const int smem_pro  = 2 * 64 * PSTR * 4;                   // 69632
    const int smem_main = 1024 + 1024 + 2 * 8192 + 2 * 16384;  // 51200
    cudaFuncSetAttribute(v2h_prologue, cudaFuncAttributeMaxDynamicSharedMemorySize, smem_pro);
    cudaFuncSetAttribute(v2h_main,     cudaFuncAttributeMaxDynamicSharedMemorySize, smem_main);

    v2h_prologue<<<128, 256, smem_pro>>>(X, W);
    v2h_main<<<256, 256, smem_main>>>(adj, bias, out);
}